// round 7
// baseline (speedup 1.0000x reference)
#include <cuda_runtime.h>
#include <cuda_fp16.h>
#include <cstdint>

// NTXentLoss fused, FP8 mma.sync edition. B=8192, D=128, G=16, T=0.5
//   prep:   one warp per row: normalize, fold 2*log2e into zis, cast e4m3;
//           exact fp32 diag cosine.
//   main:   128 CTAs (64 row-tiles x 2 col halves) x 512 threads.
//           Per 128-col chunk: mma.sync.m16n8k32.e4m3 (A from gmem regs,
//           B via 4-deep cp.async ring + ldmatrix-b16 view), fused
//           ex2.approx epilogue + block mask + per-row sums.
//   final:  per-row: loss = ln(S_neg + exp(2*diag)) - 2*diag; reduce.
// logits are in log2 domain: acc = (sim/T)*log2e, exp = exp2(acc).

#define B_N 8192
#define D_K 128
#define TILE_M 128
#define NCH 32                       // 128-col chunks per CTA (half = 4096 cols)
#define LOG2E 1.4426950408889634f
#define CHUNK_BYTES (128 * 128)      // 16 KB fp8 B chunk
#define SM_ROWSUM (4 * CHUNK_BYTES)  // ring of 4 chunks first
#define SMEM_TOTAL (SM_ROWSUM + 256 * 4)

__device__ uint32_t g_a8[B_N * 32];  // zis e4m3, scaled by (1/norm)*2*log2e
__device__ uint32_t g_b8[B_N * 32];  // zjs e4m3, scaled by (1/norm)
__device__ float g_diag[B_N];        // exact fp32 cosine(zis_i, zjs_i)
__device__ float g_rowsum[2][B_N];   // per-column-half negative exp-sums

__device__ __forceinline__ uint32_t smem_u32(const void* p) {
    return (uint32_t)__cvta_generic_to_shared(p);
}
__device__ __forceinline__ float ex2f(float x) {
    float r;
    asm("ex2.approx.ftz.f32 %0, %1;" : "=f"(r) : "f"(x));
    return r;
}

// ---------------------------------------------------------------------------
// prep: one warp per row; e4m3 conversion + exact diag, one pass.
// ---------------------------------------------------------------------------
__global__ void __launch_bounds__(256) prep_kernel(const float* __restrict__ zis,
                                                   const float* __restrict__ zjs) {
    int row = (blockIdx.x * 256 + threadIdx.x) >> 5;
    int lane = threadIdx.x & 31;
    float4 vi = reinterpret_cast<const float4*>(zis)[row * (D_K / 4) + lane];
    float4 vj = reinterpret_cast<const float4*>(zjs)[row * (D_K / 4) + lane];
    float a2 = vi.x * vi.x + vi.y * vi.y + vi.z * vi.z + vi.w * vi.w;
    float b2 = vj.x * vj.x + vj.y * vj.y + vj.z * vj.z + vj.w * vj.w;
    float d  = vi.x * vj.x + vi.y * vj.y + vi.z * vj.z + vi.w * vj.w;
#pragma unroll
    for (int o = 16; o; o >>= 1) {
        a2 += __shfl_xor_sync(0xffffffffu, a2, o);
        b2 += __shfl_xor_sync(0xffffffffu, b2, o);
        d  += __shfl_xor_sync(0xffffffffu, d, o);
    }
    float si = rsqrtf(fmaxf(a2, 1e-24f)) * (2.0f * LOG2E);
    float sj = rsqrtf(fmaxf(b2, 1e-24f));
    uint16_t lo, hi;
    asm("cvt.rn.satfinite.e4m3x2.f32 %0, %1, %2;" : "=h"(lo) : "f"(vi.y * si), "f"(vi.x * si));
    asm("cvt.rn.satfinite.e4m3x2.f32 %0, %1, %2;" : "=h"(hi) : "f"(vi.w * si), "f"(vi.z * si));
    g_a8[row * 32 + lane] = (uint32_t)lo | ((uint32_t)hi << 16);
    asm("cvt.rn.satfinite.e4m3x2.f32 %0, %1, %2;" : "=h"(lo) : "f"(vj.y * sj), "f"(vj.x * sj));
    asm("cvt.rn.satfinite.e4m3x2.f32 %0, %1, %2;" : "=h"(hi) : "f"(vj.w * sj), "f"(vj.z * sj));
    g_b8[row * 32 + lane] = (uint32_t)lo | ((uint32_t)hi << 16);
    if (lane == 0)
        g_diag[row] = d / fmaxf(sqrtf(a2) * sqrtf(b2), 1e-8f);
}

// ---------------------------------------------------------------------------
// stage one 128-col x 128-byte fp8 B chunk. Row j = 8 x 16B; swizzle c^(j&7).
// ---------------------------------------------------------------------------
__device__ __forceinline__ void stage_chunk(uint32_t smbase, int colbase, int tid) {
#pragma unroll
    for (int i = 0; i < 2; i++) {
        int u = tid + i * 512;
        int j = u >> 3, c = u & 7;
        const void* src = (const char*)g_b8 + (colbase + j) * 128 + c * 16;
        uint32_t dst = smbase + (((j << 3) + (c ^ (j & 7))) << 4);
        asm volatile("cp.async.cg.shared.global [%0], [%1], 16;" :: "r"(dst), "l"(src));
    }
    asm volatile("cp.async.commit_group;");
}

// ---------------------------------------------------------------------------
// main: 128 CTAs x 512 threads (16 warps, 4/SMSP).
// Warp (wr, wc): wr=warp&7 -> 16 rows, wc=warp>>3 -> 64 of 128 chunk cols.
// ---------------------------------------------------------------------------
__global__ void __launch_bounds__(512, 1) main_kernel() {
    extern __shared__ __align__(1024) unsigned char sm[];
    const uint32_t smb = smem_u32(sm);
    float* rowsum_sm = reinterpret_cast<float*>(sm + SM_ROWSUM);

    const int tid = threadIdx.x;
    const int lane = tid & 31;
    const int warp = tid >> 5;
    const int wr = warp & 7;
    const int wc = warp >> 3;
    const int g = lane >> 2;
    const int t4 = lane & 3;

    const int rowtile = blockIdx.x >> 1;
    const int half = blockIdx.x & 1;
    const int rb = rowtile * TILE_M;
    const int col0 = half * 4096;
    const int mask_chunk = ((rb >> 12) == half) ? ((rb & 4095) >> 7) : -1;

    // A fragments direct from gmem: 4 k-steps x 4 u32 (4 e4m3 each)
    uint32_t aF[4][4];
    {
        const int r0 = rb + wr * 16 + g, r1 = r0 + 8;
#pragma unroll
        for (int ks = 0; ks < 4; ks++) {
            aF[ks][0] = g_a8[r0 * 32 + ks * 8 + t4];
            aF[ks][1] = g_a8[r1 * 32 + ks * 8 + t4];
            aF[ks][2] = g_a8[r0 * 32 + ks * 8 + 4 + t4];
            aF[ks][3] = g_a8[r1 * 32 + ks * 8 + 4 + t4];
        }
    }

    stage_chunk(smb, col0, tid);
    stage_chunk(smb + CHUNK_BYTES, col0 + 128, tid);

    float rs0 = 0.f, rs1 = 0.f;
    const int nb = wc * 64;

    for (int m = 0; m < NCH; m++) {
        if (m < NCH - 1) asm volatile("cp.async.wait_group 1;");
        else             asm volatile("cp.async.wait_group 0;");
        __syncthreads();   // chunk m staged; all warps past epilogue(m-1)

        if (m + 2 < NCH)
            stage_chunk(smb + ((m + 2) & 3) * CHUNK_BYTES, col0 + (m + 2) * 128, tid);

        const uint32_t base = smb + (m & 3) * CHUNK_BYTES;
        float acc[8][4];
#pragma unroll
        for (int f = 0; f < 8; f++)
#pragma unroll
            for (int e = 0; e < 4; e++) acc[f][e] = 0.f;

#pragma unroll
        for (int ks = 0; ks < 4; ks++) {
            uint32_t bF[8][2];
#pragma unroll
            for (int nf = 0; nf < 4; nf++) {
                int j = nb + nf * 16 + ((lane >> 4) << 3) + (lane & 7);
                int c = 2 * ks + ((lane >> 3) & 1);
                uint32_t addr = base + (((j << 3) + (c ^ (j & 7))) << 4);
                uint32_t r0, r1, r2, r3;
                asm volatile("ldmatrix.sync.aligned.m8n8.x4.shared.b16 {%0,%1,%2,%3}, [%4];"
                             : "=r"(r0), "=r"(r1), "=r"(r2), "=r"(r3) : "r"(addr));
                bF[nf * 2][0] = r0;     bF[nf * 2][1] = r1;
                bF[nf * 2 + 1][0] = r2; bF[nf * 2 + 1][1] = r3;
            }
#pragma unroll
            for (int f = 0; f < 8; f++) {
                asm volatile(
                    "mma.sync.aligned.m16n8k32.row.col.f32.e4m3.e4m3.f32 "
                    "{%0,%1,%2,%3},{%4,%5,%6,%7},{%8,%9},{%0,%1,%2,%3};"
                    : "+f"(acc[f][0]), "+f"(acc[f][1]), "+f"(acc[f][2]), "+f"(acc[f][3])
                    : "r"(aF[ks][0]), "r"(aF[ks][1]), "r"(aF[ks][2]), "r"(aF[ks][3]),
                      "r"(bF[f][0]), "r"(bF[f][1]));
            }
        }

        if (m != mask_chunk) {
            // vector epilogue: f16x2 ex2, half2 partial sums (chunk-local, <=64)
            __half2 h0 = __float2half2_rn(0.f), h1 = h0;
#pragma unroll
            for (int f = 0; f < 8; f++) {
                uint32_t p, q;
                asm("cvt.rn.f16x2.f32 %0, %1, %2;" : "=r"(p) : "f"(acc[f][1]), "f"(acc[f][0]));
                asm("ex2.approx.f16x2 %0, %0;" : "+r"(p));
                h0 = __hadd2(h0, *reinterpret_cast<__half2*>(&p));
                asm("cvt.rn.f16x2.f32 %0, %1, %2;" : "=r"(q) : "f"(acc[f][3]), "f"(acc[f][2]));
                asm("ex2.approx.f16x2 %0, %0;" : "+r"(q));
                h1 = __hadd2(h1, *reinterpret_cast<__half2*>(&q));
            }
            float2 f0 = __half22float2(h0), f1 = __half22float2(h1);
            rs0 += f0.x + f0.y;
            rs1 += f1.x + f1.y;
        } else {
            // scalar masked epilogue (1 chunk per CTA at most)
            const int r0g = rb + wr * 16 + g, r1g = r0g + 8;
            const int cb = col0 + m * 128;
#pragma unroll
            for (int f = 0; f < 8; f++) {
                int c0 = cb + nb + f * 8 + 2 * t4;
#pragma unroll
                for (int e = 0; e < 4; e++) {
                    int r = (e < 2) ? r0g : r1g;
                    int c = c0 + (e & 1);
                    float ev = ex2f(acc[f][e]);
                    if ((r >> 4) == (c >> 4)) ev = 0.f;  // whole own block (diag incl.)
                    if (e < 2) rs0 += ev; else rs1 += ev;
                }
            }
        }
    }

    // quad reduction: lanes 4g..4g+3 hold cols of the same rows
    rs0 += __shfl_xor_sync(0xffffffffu, rs0, 1);
    rs0 += __shfl_xor_sync(0xffffffffu, rs0, 2);
    rs1 += __shfl_xor_sync(0xffffffffu, rs1, 1);
    rs1 += __shfl_xor_sync(0xffffffffu, rs1, 2);
    if (t4 == 0) {
        rowsum_sm[wc * 128 + wr * 16 + g] = rs0;
        rowsum_sm[wc * 128 + wr * 16 + g + 8] = rs1;
    }
    __syncthreads();
    if (tid < 128)
        g_rowsum[half][rb + tid] = rowsum_sm[tid] + rowsum_sm[128 + tid];
}

// ---------------------------------------------------------------------------
// finalize: per-row loss + reduction
// ---------------------------------------------------------------------------
__global__ void __launch_bounds__(1024) finalize_kernel(float* __restrict__ out) {
    __shared__ float red[1024];
    int tid = threadIdx.x;
    float t = 0.f;
    for (int r = tid; r < B_N; r += 1024) {
        float S = g_rowsum[0][r] + g_rowsum[1][r];
        float d = g_diag[r];
        float pos = 2.0f * d;              // sim / T
        S += ex2f(pos * LOG2E);            // add positive term
        t += logf(S) - pos;
    }
    red[tid] = t;
    __syncthreads();
    for (int o = 512; o; o >>= 1) {
        if (tid < o) red[tid] += red[tid + o];
        __syncthreads();
    }
    if (tid == 0) out[0] = red[0] * (1.0f / (float)B_N);
}

extern "C" void kernel_launch(void* const* d_in, const int* in_sizes, int n_in,
                              void* d_out, int out_size) {
    (void)in_sizes; (void)n_in; (void)out_size;
    const float* zis = (const float*)d_in[0];
    const float* zjs = (const float*)d_in[1];
    cudaFuncSetAttribute(main_kernel, cudaFuncAttributeMaxDynamicSharedMemorySize,
                         SMEM_TOTAL);
    prep_kernel<<<B_N * 32 / 256, 256>>>(zis, zjs);   // 1024 blocks
    main_kernel<<<128, 512, SMEM_TOTAL>>>();
    finalize_kernel<<<1, 1024>>>((float*)d_out);
}